// round 6
// baseline (speedup 1.0000x reference)
#include <cuda_runtime.h>
#include <cstdint>
#include <cstddef>

#define T_STEPS 4096
#define IN_DIM  128
#define HIDDEN  2048
#define LEAK    0.9f
#define NCTA    128
#define TPB     512
#define ROWS_PER_CTA 16   // HIDDEN / NCTA

// ---------------- device scratch (static: no allocations allowed) ----------------
__device__ float g_inp[(size_t)T_STEPS * HIDDEN];   // precomputed input projection [T,H]

// One 128B line per (parity, producer CTA): 16 act values + step tag.
struct __align__(128) ActLine {
    float act[16];
    unsigned int tag;
    unsigned int pad[15];
};
__device__ ActLine g_lines[2][NCTA];                // 32 KB, L2-resident

// ---------------- packed fp32x2 helpers ----------------
__device__ __forceinline__ unsigned long long pack2(float lo, float hi) {
    unsigned long long u;
    asm("mov.b64 %0, {%1, %2};" : "=l"(u) : "f"(lo), "f"(hi));
    return u;
}
__device__ __forceinline__ void unpack2(unsigned long long u, float& lo, float& hi) {
    asm("mov.b64 {%0, %1}, %2;" : "=f"(lo), "=f"(hi) : "l"(u));
}
__device__ __forceinline__ unsigned long long ffma2(unsigned long long a,
                                                    unsigned long long b,
                                                    unsigned long long c) {
    unsigned long long d;
    asm("fma.rn.f32x2 %0, %1, %2, %3;" : "=l"(d) : "l"(a), "l"(b), "l"(c));
    return d;
}

// ---------------- release/acquire primitives (no fences, no atomics) ----------------
__device__ __forceinline__ void st_release_u32(unsigned int* p, unsigned int v) {
    asm volatile("st.release.gpu.global.u32 [%0], %1;" :: "l"(p), "r"(v) : "memory");
}
__device__ __forceinline__ unsigned int ld_acquire_u32(const unsigned int* p) {
    unsigned int v;
    asm volatile("ld.acquire.gpu.global.u32 %0, [%1];" : "=r"(v) : "l"(p) : "memory");
    return v;
}

// ---------------- reset: zero all tags (stream-ordered, replay-safe) ----------------
__global__ void reset_kernel() {
    const int i = threadIdx.x;   // 256 threads = 2*NCTA tags exactly
    g_lines[i >> 7][i & 127].tag = 0u;
}

// ---------------- phase A: inp_proj[t][h] = input[t,:] . w_ih[h,:] + b_ih[h] ----------------
__global__ void inp_proj_kernel(const float* __restrict__ input,
                                const float* __restrict__ w_ih,
                                const float* __restrict__ b_ih) {
    __shared__ float s_in[16 * IN_DIM];
    const int tblk = blockIdx.x;
    const int tid  = threadIdx.x;

    for (int i = tid; i < 16 * IN_DIM; i += 256)
        s_in[i] = input[(size_t)tblk * 16 * IN_DIM + i];
    __syncthreads();

    const float4* s_in4 = reinterpret_cast<const float4*>(s_in);

    for (int j = 0; j < 8; j++) {
        const int h = tid + 256 * j;
        float acc[16];
        const float b = b_ih[h];
#pragma unroll
        for (int t = 0; t < 16; t++) acc[t] = b;

        const float4* wrow = reinterpret_cast<const float4*>(w_ih + (size_t)h * IN_DIM);
#pragma unroll 4
        for (int kc = 0; kc < IN_DIM / 4; kc++) {
            const float4 w4 = wrow[kc];
#pragma unroll
            for (int t = 0; t < 16; t++) {
                const float4 iv = s_in4[t * (IN_DIM / 4) + kc];  // warp-broadcast
                acc[t] += w4.x * iv.x + w4.y * iv.y + w4.z * iv.z + w4.w * iv.w;
            }
        }
#pragma unroll
        for (int t = 0; t < 16; t++)
            g_inp[(size_t)(tblk * 16 + t) * HIDDEN + h] = acc[t];
    }
}

// ---------------- phase B: persistent recurrence, distributed line-tag sync ----------------
// 128 CTAs x 512 threads. CTA b owns rows [16b, 16b+16); thread tid owns all
// 16 rows x cols [4*tid, 4*tid+4) (64 weights in regs).
// Producer (warp 0, lanes<16): line.act[] stores, syncwarp, st.release tag=t+1.
// Consumer (every thread): ld.acquire-poll tag of source CTA (tid/4) >= t,
// then __ldcg the float4 from the same line. Warp 2 duplicates the finalize
// math and handles out_act/out_hid off the critical path.
__global__ void __launch_bounds__(TPB, 1)
reservoir_kernel(const float* __restrict__ w_hh,
                 float* __restrict__ out_act,
                 float* __restrict__ out_hid) {
    __shared__ float s_part[2][ROWS_PER_CTA][17];   // parity double-buffered

    const int tid  = threadIdx.x;
    const int lane = tid & 31;
    const int w    = tid >> 5;                   // warp id 0..15
    const int cta  = blockIdx.x;
    const int base_row = cta * ROWS_PER_CTA;

    // Load weights: W[r] = cols [4*tid, 4*tid+4) of row base_row + r.
    unsigned long long W[ROWS_PER_CTA][2];
#pragma unroll
    for (int r = 0; r < ROWS_PER_CTA; r++) {
        const float4 wv = reinterpret_cast<const float4*>(
            w_hh + (size_t)(base_row + r) * HIDDEN)[tid];
        W[r][0] = pack2(wv.x, wv.y);
        W[r][1] = pack2(wv.z, wv.w);
    }

    const int fin_row = base_row + lane;   // finalize row (lanes<16 of warps 0,2)
    float hid = 0.0f;                      // identical copies in warps 0 and 2

    // ---- t = 0 peeled: previous act is the zero vector -> dot = 0 ----
    if (lane < ROWS_PER_CTA && (w == 0 || w == 2)) {
        const float u0 = g_inp[fin_row];
        const float nh = LEAK * u0;
        const float na = tanhf(nh);
        hid = nh;
        if (w == 0) {
            g_lines[0][cta].act[lane] = na;
            __syncwarp(0x0000ffffu);
            if (lane == 0) st_release_u32(&g_lines[0][cta].tag, 1u);
        } else {
            out_act[fin_row] = na;
            out_hid[fin_row] = nh;
        }
    }

    const int src_cta = tid >> 2;          // source CTA for this thread's 4 cols
    const int src_off = tid & 3;           // float4 index within the line

    for (int t = 1; t < T_STEPS; t++) {
        // prefetch u_t (warps 0 and 2 only; hidden under the poll)
        float u = 0.0f;
        if (lane < ROWS_PER_CTA && (w == 0 || w == 2))
            u = g_inp[(size_t)t * HIDDEN + fin_row];

        // ---- per-thread poll: source line for act_{t-1} (parity (t-1)&1, tag >= t) ----
        const ActLine* src = &g_lines[(t + 1) & 1][src_cta];
        {
            const unsigned int tgt = (unsigned int)t;
            unsigned int tg = ld_acquire_u32(&src->tag);
            while (tg < tgt) {
                tg = ld_acquire_u32(&src->tag);
                if (tg >= tgt) break;
                tg = ld_acquire_u32(&src->tag);
            }
        }
        const float4 a = __ldcg(reinterpret_cast<const float4*>(src->act) + src_off);
        const unsigned long long A0 = pack2(a.x, a.y);
        const unsigned long long A1 = pack2(a.z, a.w);

        // ---- 16 independent 2-deep FFMA2 chains ----
        float v[ROWS_PER_CTA];
#pragma unroll
        for (int r = 0; r < ROWS_PER_CTA; r++) {
            unsigned long long P = ffma2(W[r][0], A0, 0ull);
            P = ffma2(W[r][1], A1, P);
            float lo, hi; unpack2(P, lo, hi);
            v[r] = lo + hi;
        }

        // ---- value-splitting warp butterfly: 16 values -> 1 per lane ----
        {
            const bool up = (lane & 16) != 0;
#pragma unroll
            for (int i = 0; i < 8; i++) {
                const float send = up ? v[i] : v[i + 8];
                const float recv = __shfl_xor_sync(0xffffffffu, send, 16);
                v[i] = (up ? v[i + 8] : v[i]) + recv;
            }
        }
        {
            const bool up = (lane & 8) != 0;
#pragma unroll
            for (int i = 0; i < 4; i++) {
                const float send = up ? v[i] : v[i + 4];
                const float recv = __shfl_xor_sync(0xffffffffu, send, 8);
                v[i] = (up ? v[i + 4] : v[i]) + recv;
            }
        }
        {
            const bool up = (lane & 4) != 0;
#pragma unroll
            for (int i = 0; i < 2; i++) {
                const float send = up ? v[i] : v[i + 2];
                const float recv = __shfl_xor_sync(0xffffffffu, send, 4);
                v[i] = (up ? v[i + 2] : v[i]) + recv;
            }
        }
        {
            const bool up = (lane & 2) != 0;
            const float send = up ? v[0] : v[1];
            const float recv = __shfl_xor_sync(0xffffffffu, send, 2);
            v[0] = (up ? v[1] : v[0]) + recv;
        }
        v[0] += __shfl_xor_sync(0xffffffffu, v[0], 1);

        const int vrow = (lane >> 1) & 15;
        if ((lane & 1) == 0) s_part[t & 1][vrow][w] = v[0];
        __syncthreads();   // the ONLY block barrier per step

        // ---- finalize (warps 0 and 2, lanes<16) ----
        if (lane < ROWS_PER_CTA && (w == 0 || w == 2)) {
            float d0 = 0.0f, d1 = 0.0f, d2 = 0.0f, d3 = 0.0f;
#pragma unroll
            for (int j = 0; j < 4; j++) {
                d0 += s_part[t & 1][lane][j];
                d1 += s_part[t & 1][lane][j + 4];
                d2 += s_part[t & 1][lane][j + 8];
                d3 += s_part[t & 1][lane][j + 12];
            }
            const float dot = (d0 + d1) + (d2 + d3);
            const float nh = (1.0f - LEAK) * hid + LEAK * (u + dot);
            const float na = tanhf(nh);
            hid = nh;
            if (w == 0) {
                // critical path: publish line + release tag
                g_lines[t & 1][cta].act[lane] = na;
                __syncwarp(0x0000ffffu);
                if (lane == 0) st_release_u32(&g_lines[t & 1][cta].tag,
                                              (unsigned int)(t + 1));
            } else {
                // off critical path: result tensors
                out_act[(size_t)t * HIDDEN + fin_row] = na;
                out_hid[(size_t)t * HIDDEN + fin_row] = nh;
            }
        }
        // s_part anti-overwrite is guaranteed by parity double-buffering:
        // slot (t&1) is next written at t+2, after syncthreads(t+1), which
        // warp 0/2 join only after finishing these reads.
    }
}

// ---------------- launch ----------------
extern "C" void kernel_launch(void* const* d_in, const int* in_sizes, int n_in,
                              void* d_out, int out_size) {
    const float* input = (const float*)d_in[0];   // [T, IN_DIM]
    const float* w_ih  = (const float*)d_in[1];   // [H, IN_DIM]
    const float* b_ih  = (const float*)d_in[2];   // [H]
    const float* w_hh  = (const float*)d_in[3];   // [H, H]

    float* out_act = (float*)d_out;                            // [T, H]
    float* out_hid = (float*)d_out + (size_t)T_STEPS * HIDDEN; // [T, H]

    reset_kernel<<<1, 256>>>();
    inp_proj_kernel<<<T_STEPS / 16, 256>>>(input, w_ih, b_ih);
    reservoir_kernel<<<NCTA, TPB>>>(w_hh, out_act, out_hid);
}

// round 7
// speedup vs baseline: 1.0717x; 1.0717x over previous
#include <cuda_runtime.h>
#include <cstdint>
#include <cstddef>

#define T_STEPS 4096
#define IN_DIM  128
#define HIDDEN  2048
#define LEAK    0.9f
#define NCTA    128
#define TPB     512
#define ROWS_PER_CTA 16   // HIDDEN / NCTA

// ---------------- device scratch (static: no allocations allowed) ----------------
__device__ float g_inp[(size_t)T_STEPS * HIDDEN];   // precomputed input projection [T,H]

// One 128B line per (parity, producer CTA): 16 act values + step tag.
struct __align__(128) ActLine {
    float act[16];
    unsigned int tag;
    unsigned int pad[15];
};
__device__ ActLine g_lines[2][NCTA];                // 32 KB, L2-resident

// ---------------- packed fp32x2 helpers ----------------
__device__ __forceinline__ unsigned long long pack2(float lo, float hi) {
    unsigned long long u;
    asm("mov.b64 %0, {%1, %2};" : "=l"(u) : "f"(lo), "f"(hi));
    return u;
}
__device__ __forceinline__ void unpack2(unsigned long long u, float& lo, float& hi) {
    asm("mov.b64 {%0, %1}, %2;" : "=f"(lo), "=f"(hi) : "l"(u));
}
__device__ __forceinline__ unsigned long long ffma2(unsigned long long a,
                                                    unsigned long long b,
                                                    unsigned long long c) {
    unsigned long long d;
    asm("fma.rn.f32x2 %0, %1, %2, %3;" : "=l"(d) : "l"(a), "l"(b), "l"(c));
    return d;
}

// ---------------- release/acquire primitives (no fences, no atomics) ----------------
__device__ __forceinline__ void st_release_u32(unsigned int* p, unsigned int v) {
    asm volatile("st.release.gpu.global.u32 [%0], %1;" :: "l"(p), "r"(v) : "memory");
}
__device__ __forceinline__ unsigned int ld_acquire_u32(const unsigned int* p) {
    unsigned int v;
    asm volatile("ld.acquire.gpu.global.u32 %0, [%1];" : "=r"(v) : "l"(p) : "memory");
    return v;
}

// ---------------- reset: zero all tags (stream-ordered, replay-safe) ----------------
__global__ void reset_kernel() {
    const int i = threadIdx.x;   // 256 threads = 2*NCTA tags exactly
    g_lines[i >> 7][i & 127].tag = 0u;
}

// ---------------- phase A: inp_proj[t][h] = input[t,:] . w_ih[h,:] + b_ih[h] ----------------
__global__ void inp_proj_kernel(const float* __restrict__ input,
                                const float* __restrict__ w_ih,
                                const float* __restrict__ b_ih) {
    __shared__ float s_in[16 * IN_DIM];
    const int tblk = blockIdx.x;
    const int tid  = threadIdx.x;

    for (int i = tid; i < 16 * IN_DIM; i += 256)
        s_in[i] = input[(size_t)tblk * 16 * IN_DIM + i];
    __syncthreads();

    const float4* s_in4 = reinterpret_cast<const float4*>(s_in);

    for (int j = 0; j < 8; j++) {
        const int h = tid + 256 * j;
        float acc[16];
        const float b = b_ih[h];
#pragma unroll
        for (int t = 0; t < 16; t++) acc[t] = b;

        const float4* wrow = reinterpret_cast<const float4*>(w_ih + (size_t)h * IN_DIM);
#pragma unroll 4
        for (int kc = 0; kc < IN_DIM / 4; kc++) {
            const float4 w4 = wrow[kc];
#pragma unroll
            for (int t = 0; t < 16; t++) {
                const float4 iv = s_in4[t * (IN_DIM / 4) + kc];  // warp-broadcast
                acc[t] += w4.x * iv.x + w4.y * iv.y + w4.z * iv.z + w4.w * iv.w;
            }
        }
#pragma unroll
        for (int t = 0; t < 16; t++)
            g_inp[(size_t)(tblk * 16 + t) * HIDDEN + h] = acc[t];
    }
}

// ---------------- phase B: persistent recurrence kernel ----------------
// 128 CTAs x 512 threads. CTA b owns rows [16b, 16b+16); thread tid owns all
// 16 rows x cols [4*tid, 4*tid+4) (64 weights in regs).
// Sync: producer warp 0 publishes its 16 acts + tag in ONE 128B line
// (plain stores + st.release tag). ONE poller warp (warp 15) per CTA sweeps
// the 128 tags (32 lanes x 4 ld.acquire); __syncthreads releases the CTA;
// every thread then __ldcg's its float4 from its source line.
// No atomics, no fences, poll population = 1 warp/CTA.
__global__ void __launch_bounds__(TPB, 1)
reservoir_kernel(const float* __restrict__ w_hh,
                 float* __restrict__ out_act,
                 float* __restrict__ out_hid) {
    __shared__ float s_part[2][ROWS_PER_CTA][17];   // parity double-buffered

    const int tid  = threadIdx.x;
    const int lane = tid & 31;
    const int w    = tid >> 5;                   // warp id 0..15
    const int cta  = blockIdx.x;
    const int base_row = cta * ROWS_PER_CTA;

    // Load weights: W[r] = cols [4*tid, 4*tid+4) of row base_row + r.
    unsigned long long W[ROWS_PER_CTA][2];
#pragma unroll
    for (int r = 0; r < ROWS_PER_CTA; r++) {
        const float4 wv = reinterpret_cast<const float4*>(
            w_hh + (size_t)(base_row + r) * HIDDEN)[tid];
        W[r][0] = pack2(wv.x, wv.y);
        W[r][1] = pack2(wv.z, wv.w);
    }

    const int fin_row = base_row + lane;   // finalize row (lanes<16 of warps 0,2)
    float hid = 0.0f;                      // identical copies in warps 0 and 2

    // ---- t = 0 peeled: previous act is the zero vector -> dot = 0 ----
    if (lane < ROWS_PER_CTA && (w == 0 || w == 2)) {
        const float u0 = g_inp[fin_row];
        const float nh = LEAK * u0;
        const float na = tanhf(nh);
        hid = nh;
        if (w == 0) {
            g_lines[0][cta].act[lane] = na;
            __syncwarp(0x0000ffffu);
            if (lane == 0) st_release_u32(&g_lines[0][cta].tag, 1u);
        } else {
            out_act[fin_row] = na;
            out_hid[fin_row] = nh;
        }
    }

    const int src_cta = tid >> 2;          // source CTA for this thread's 4 cols
    const int src_off = tid & 3;           // float4 index within the line

    for (int t = 1; t < T_STEPS; t++) {
        // prefetch u_t (warps 0 and 2 only; issued before the wait)
        float u = 0.0f;
        if (lane < ROWS_PER_CTA && (w == 0 || w == 2))
            u = g_inp[(size_t)t * HIDDEN + fin_row];

        // ---- poller warp 15: sweep all 128 tags for act_{t-1} ----
        // (runs concurrent with other CTAs' finalize; joins local warps at bar)
        if (w == 15) {
            const ActLine* lines = g_lines[(t + 1) & 1];
            const unsigned int tgt = (unsigned int)t;
            bool ok;
            do {
                const unsigned int t0 = ld_acquire_u32(&lines[lane      ].tag);
                const unsigned int t1 = ld_acquire_u32(&lines[lane + 32 ].tag);
                const unsigned int t2 = ld_acquire_u32(&lines[lane + 64 ].tag);
                const unsigned int t3 = ld_acquire_u32(&lines[lane + 96 ].tag);
                ok = (t0 >= tgt) & (t1 >= tgt) & (t2 >= tgt) & (t3 >= tgt);
            } while (!__all_sync(0xffffffffu, ok));
        }
        __syncthreads();   // (A) all source lines published; release to CTA

        // act slice straight into registers (L2-coherent, line is hot)
        const float4 a = __ldcg(
            reinterpret_cast<const float4*>(g_lines[(t + 1) & 1][src_cta].act) + src_off);
        const unsigned long long A0 = pack2(a.x, a.y);
        const unsigned long long A1 = pack2(a.z, a.w);

        // ---- 16 independent 2-deep FFMA2 chains ----
        float v[ROWS_PER_CTA];
#pragma unroll
        for (int r = 0; r < ROWS_PER_CTA; r++) {
            unsigned long long P = ffma2(W[r][0], A0, 0ull);
            P = ffma2(W[r][1], A1, P);
            float lo, hi; unpack2(P, lo, hi);
            v[r] = lo + hi;
        }

        // ---- value-splitting warp butterfly: 16 values -> 1 per lane ----
        {
            const bool up = (lane & 16) != 0;
#pragma unroll
            for (int i = 0; i < 8; i++) {
                const float send = up ? v[i] : v[i + 8];
                const float recv = __shfl_xor_sync(0xffffffffu, send, 16);
                v[i] = (up ? v[i + 8] : v[i]) + recv;
            }
        }
        {
            const bool up = (lane & 8) != 0;
#pragma unroll
            for (int i = 0; i < 4; i++) {
                const float send = up ? v[i] : v[i + 4];
                const float recv = __shfl_xor_sync(0xffffffffu, send, 8);
                v[i] = (up ? v[i + 4] : v[i]) + recv;
            }
        }
        {
            const bool up = (lane & 4) != 0;
#pragma unroll
            for (int i = 0; i < 2; i++) {
                const float send = up ? v[i] : v[i + 2];
                const float recv = __shfl_xor_sync(0xffffffffu, send, 4);
                v[i] = (up ? v[i + 2] : v[i]) + recv;
            }
        }
        {
            const bool up = (lane & 2) != 0;
            const float send = up ? v[0] : v[1];
            const float recv = __shfl_xor_sync(0xffffffffu, send, 2);
            v[0] = (up ? v[1] : v[0]) + recv;
        }
        v[0] += __shfl_xor_sync(0xffffffffu, v[0], 1);

        const int vrow = (lane >> 1) & 15;
        if ((lane & 1) == 0) s_part[t & 1][vrow][w] = v[0];
        __syncthreads();   // (B) s_part ready; poller proceeds to next poll

        // ---- finalize (warps 0 and 2, lanes<16) ----
        if (lane < ROWS_PER_CTA && (w == 0 || w == 2)) {
            float d0 = 0.0f, d1 = 0.0f, d2 = 0.0f, d3 = 0.0f;
#pragma unroll
            for (int j = 0; j < 4; j++) {
                d0 += s_part[t & 1][lane][j];
                d1 += s_part[t & 1][lane][j + 4];
                d2 += s_part[t & 1][lane][j + 8];
                d3 += s_part[t & 1][lane][j + 12];
            }
            const float dot = (d0 + d1) + (d2 + d3);
            const float nh = (1.0f - LEAK) * hid + LEAK * (u + dot);
            const float na = tanhf(nh);
            hid = nh;
            if (w == 0) {
                // critical path: publish line + release tag
                g_lines[t & 1][cta].act[lane] = na;
                __syncwarp(0x0000ffffu);
                if (lane == 0) st_release_u32(&g_lines[t & 1][cta].tag,
                                              (unsigned int)(t + 1));
            } else {
                // off critical path: result tensors
                out_act[(size_t)t * HIDDEN + fin_row] = na;
                out_hid[(size_t)t * HIDDEN + fin_row] = nh;
            }
        }
        // s_part anti-overwrite: parity slot (t&1) is rewritten at t+2 only
        // after bar (A) of step t+2, which warps 0/2 reach after these reads.
        // Cross-CTA line anti-overwrite: producer at t+2 overwrites parity
        // (t&1) only after acquiring every CTA's tag t+1, released after
        // their step-t reads of that line completed.
    }
}

// ---------------- launch ----------------
extern "C" void kernel_launch(void* const* d_in, const int* in_sizes, int n_in,
                              void* d_out, int out_size) {
    const float* input = (const float*)d_in[0];   // [T, IN_DIM]
    const float* w_ih  = (const float*)d_in[1];   // [H, IN_DIM]
    const float* b_ih  = (const float*)d_in[2];   // [H]
    const float* w_hh  = (const float*)d_in[3];   // [H, H]

    float* out_act = (float*)d_out;                            // [T, H]
    float* out_hid = (float*)d_out + (size_t)T_STEPS * HIDDEN; // [T, H]

    reset_kernel<<<1, 256>>>();
    inp_proj_kernel<<<T_STEPS / 16, 256>>>(input, w_ih, b_ih);
    reservoir_kernel<<<NCTA, TPB>>>(w_hh, out_act, out_hid);
}